// round 7
// baseline (speedup 1.0000x reference)
#include <cuda_runtime.h>
#include <cuda_fp16.h>

// HashGridEncoder2D: L=16, F=2, N=1048576, T=524288. fp16 tables scaled by 4096.
// R7: spatial bucketing (32x32 uv tiles, 1024 bins) so each warp's 32 points are
// spatially coherent -> dense-level gathers touch few 128B lines. Structure of the
// main kernel = R5 (slot-warp, 32 pts/block, one transpose barrier).
// Levels 0..11 dense: fp16 quad-packed, one 16B LDG per lookup.
// Levels 12..15 hashed (prime 131101, mod 2^19): 16B group-of-4 + weight scatter.

#define NPTS    1048576
#define TSIZE   524288
#define TMASK   (TSIZE - 1)
#define HPRIME  131101
#define QTOTAL  659835                 // sum of res^2 over dense levels 0..11
#define HBASE   663817                 // float2 index where hashed tables start
#define RPTOTAL (QTOTAL + TSIZE)
#define NBINS   1024
#define SCALE_F     4096.0f
#define INV_SCALE_F (1.0f / 4096.0f)

__constant__ int c_res[16] = {16, 22, 30, 42, 58, 80, 111, 153,
                              212, 294, 406, 561, 776, 1072, 1482, 2048};
__constant__ int c_off[16] = {0, 289, 818, 1779, 3628, 7109, 13670, 26214,
                              49930, 95299, 182324, 347973,
                              663817, 1188105, 1712393, 2236681};
__constant__ int c_qoff[12] = {0, 256, 740, 1640, 3404, 6768, 13168,
                               25489, 48898, 93842, 180278, 345114};

// 10.6 MB: dense cell (l,x,y) -> {v00,v01,v10,v11} as 4 half2 (16B aligned).
__device__ __align__(16) __half2 g_qh[(size_t)QTOTAL * 4];
// 8.4 MB: 16B-aligned fp16 mirror of the 4 hashed level tables.
__device__ __align__(16) __half2 g_hh[4 * TSIZE];

// bucketing state (rebuilt every replay)
__device__ int    g_hist[NBINS];
__device__ int    g_base[NBINS];
__device__ int    g_perm[NPTS];
__device__ __align__(8) float2 g_uvs[NPTS];

__device__ __forceinline__ __half2 sc_h2(float2 v) {
    return __floats2half2_rn(v.x * SCALE_F, v.y * SCALE_F);
}

__device__ __forceinline__ int bin_of(float2 p) {
    int kx = (int)(p.x * 32.0f);
    int ky = (int)(p.y * 32.0f);
    kx = min(kx, 31); ky = min(ky, 31);
    return ky * 32 + kx;
}

__global__ void zero_kernel() {
    int t = blockIdx.x * blockDim.x + threadIdx.x;
    if (t < NBINS) g_hist[t] = 0;
}

__global__ void __launch_bounds__(256)
hist_kernel(const float2* __restrict__ uv) {
    int n = blockIdx.x * blockDim.x + threadIdx.x;
    float2 p = __ldg(&uv[n]);
    atomicAdd(&g_hist[bin_of(p)], 1);
}

__global__ void __launch_bounds__(NBINS)
scan_kernel() {
    __shared__ int s[NBINS];
    int t = threadIdx.x;
    int h = g_hist[t];
    s[t] = h;
    __syncthreads();
#pragma unroll
    for (int off = 1; off < NBINS; off <<= 1) {
        int v = (t >= off) ? s[t - off] : 0;
        __syncthreads();
        s[t] += v;
        __syncthreads();
    }
    g_base[t] = s[t] - h;   // exclusive prefix
}

__global__ void __launch_bounds__(256)
scatter_kernel(const float2* __restrict__ uv) {
    int n = blockIdx.x * blockDim.x + threadIdx.x;
    float2 p = __ldg(&uv[n]);
    int pos = atomicAdd(&g_base[bin_of(p)], 1);
    g_perm[pos] = n;
    g_uvs[pos]  = p;
}

__global__ void __launch_bounds__(256)
repack_kernel(const float2* __restrict__ lat)
{
    int c = blockIdx.x * blockDim.x + threadIdx.x;
    if (c >= RPTOTAL) return;

    if (c >= QTOTAL) {
        int base = (c - QTOTAL) * 4;
        __half2 h0 = sc_h2(lat[HBASE + base + 0]);
        __half2 h1 = sc_h2(lat[HBASE + base + 1]);
        __half2 h2 = sc_h2(lat[HBASE + base + 2]);
        __half2 h3 = sc_h2(lat[HBASE + base + 3]);
        float4 v;
        ((__half2*)&v)[0] = h0; ((__half2*)&v)[1] = h1;
        ((__half2*)&v)[2] = h2; ((__half2*)&v)[3] = h3;
        *(float4*)(g_hh + base) = v;
        return;
    }

    int l = 0;
#pragma unroll
    for (int i = 1; i < 12; i++) l += (c >= c_qoff[i]);

    int local = c - c_qoff[l];
    int res   = c_res[l];
    int x     = local / res;
    int y     = local - x * res;
    int base  = c_off[l] + x * res + y;

    __half2 h00 = sc_h2(lat[base]);
    __half2 h01 = sc_h2(lat[base + 1]);
    __half2 h10 = sc_h2(lat[base + res]);
    __half2 h11 = sc_h2(lat[base + res + 1]);

    float4 v;
    ((__half2*)&v)[0] = h00; ((__half2*)&v)[1] = h01;
    ((__half2*)&v)[2] = h10; ((__half2*)&v)[3] = h11;
    *(float4*)(g_qh + (size_t)c * 4) = v;
}

__global__ void __launch_bounds__(256)
hashgrid2d_kernel(float4* __restrict__ out)
{
    __shared__ float2 s_uv[32];
    __shared__ int    s_pn[32];
    __shared__ float4 s_tr[256];

    int tid = threadIdx.x;
    int w   = tid >> 5;          // slot: levels {2w, 2w+1}
    int ln  = tid & 31;
    int n0  = blockIdx.x * 32;

    if (w == 0) {
        s_uv[ln] = g_uvs[n0 + ln];
        s_pn[ln] = g_perm[n0 + ln];
    }
    __syncthreads();
    float2 p = s_uv[ln];

    float r0, r1, r2, r3;

    if (w < 6) {
        // ---- two dense levels: one 16B quad load each ----
        float rr[4];
#pragma unroll
        for (int k = 0; k < 2; k++) {
            int l   = 2 * w + k;
            int res = c_res[l];

            float fres = (float)res;
            float sx = p.x * fres;
            float sy = p.y * fres;
            float fx = floorf(sx);
            float fy = floorf(sy);
            int   x0 = (int)fx;
            int   y0 = (int)fy;
            float px = sx - fx;
            float py = sy - fy;

            float4 raw = *(const float4*)(g_qh + (size_t)(c_qoff[l] + x0 * res + y0) * 4);
            const __half2* h = (const __half2*)&raw;
            float2 v00 = __half22float2(h[0]);
            float2 v01 = __half22float2(h[1]);
            float2 v10 = __half22float2(h[2]);
            float2 v11 = __half22float2(h[3]);

            float qx = 1.0f - px;
            float qy = 1.0f - py;
            float w00 = qx * qy;
            float w01 = qx * py;
            float w10 = px * qy;
            float w11 = px * py;

            rr[2 * k + 0] = v00.x * w00 + v01.x * w01 + v10.x * w10 + v11.x * w11;
            rr[2 * k + 1] = v00.y * w00 + v01.y * w01 + v10.y * w10 + v11.y * w11;
        }
        r0 = rr[0]; r1 = rr[1]; r2 = rr[2]; r3 = rr[3];
    } else {
        // ---- two hashed levels: 16B group-of-4 loads + weight scatter ----
        float rr[4];
#pragma unroll
        for (int k = 0; k < 2; k++) {
            int l = 12 + (w - 6) * 2 + k;

            float fres = (float)c_res[l];
            float sx = p.x * fres;
            float sy = p.y * fres;
            float fx = floorf(sx);
            float fy = floorf(sy);
            int   x0 = (int)fx;
            int   y0 = (int)fy;
            float px = sx - fx;
            float py = sy - fy;

            float qx = 1.0f - px;
            float qy = 1.0f - py;

            const __half2* H = g_hh + (size_t)(l - 12) * TSIZE;

            int hy0 = y0 * HPRIME;
            int hy1 = hy0 + HPRIME;
            int i0  = (x0 ^ hy0) & TMASK;
            int i1  = (x0 ^ hy1) & TMASK;

            float4 raw0 = *(const float4*)(H + (i0 & ~3));
            float4 raw1 = *(const float4*)(H + (i1 & ~3));
            const __half2* v0 = (const __half2*)&raw0;
            const __half2* v1 = (const __half2*)&raw1;

            int  d   = ((x0 + 1) ^ x0) & 3;        // 1 or 3
            bool ing = (x0 & 3) != 3;              // x0+1 in same 16B group?
            float wpx = ing ? px : 0.0f;

            int pA0 = i0 & 3, pB0 = pA0 ^ d;
            int pA1 = i1 & 3, pB1 = pA1 ^ d;

            float e0x = 0.f, e0y = 0.f, e1x = 0.f, e1y = 0.f;
#pragma unroll
            for (int t = 0; t < 4; t++) {
                float wt0 = (t == pA0) ? qx : ((t == pB0) ? wpx : 0.0f);
                float wt1 = (t == pA1) ? qx : ((t == pB1) ? wpx : 0.0f);
                float2 a = __half22float2(v0[t]);
                float2 b = __half22float2(v1[t]);
                e0x += wt0 * a.x; e0y += wt0 * a.y;
                e1x += wt1 * b.x; e1y += wt1 * b.y;
            }

            if (!ing) {
                int x1 = x0 + 1;
                float2 f0 = __half22float2(H[(x1 ^ hy0) & TMASK]);
                float2 f1 = __half22float2(H[(x1 ^ hy1) & TMASK]);
                e0x += px * f0.x; e0y += px * f0.y;
                e1x += px * f1.x; e1y += px * f1.y;
            }

            rr[2 * k + 0] = qy * e0x + py * e1x;
            rr[2 * k + 1] = qy * e0y + py * e1y;
        }
        r0 = rr[0]; r1 = rr[1]; r2 = rr[2]; r3 = rr[3];
    }

    r0 *= INV_SCALE_F; r1 *= INV_SCALE_F; r2 *= INV_SCALE_F; r3 *= INV_SCALE_F;

    // XOR-swizzled transpose; store to each point's ORIGINAL slot (scattered by
    // 128B line, 1 line per point -> same line count as coalesced).
    s_tr[ln * 8 + (w ^ (ln & 7))] = make_float4(r0, r1, r2, r3);
    __syncthreads();

    int jj = tid & 7;
    int ll = tid >> 3;
    int pn = s_pn[ll];
    out[(size_t)pn * 8 + jj] = s_tr[ll * 8 + (jj ^ (ll & 7))];
}

extern "C" void kernel_launch(void* const* d_in, const int* in_sizes, int n_in,
                              void* d_out, int out_size)
{
    const float2* uv  = (const float2*)d_in[0];
    const float2* lat = (const float2*)d_in[1];
    float4*       out = (float4*)d_out;

    zero_kernel<<<4, 256>>>();
    hist_kernel<<<NPTS / 256, 256>>>(uv);
    scan_kernel<<<1, NBINS>>>();
    scatter_kernel<<<NPTS / 256, 256>>>(uv);
    repack_kernel<<<(RPTOTAL + 255) / 256, 256>>>(lat);

    hashgrid2d_kernel<<<NPTS / 32, 256>>>(out);
}

// round 8
// speedup vs baseline: 2.1465x; 2.1465x over previous
#include <cuda_runtime.h>
#include <cuda_fp16.h>

// HashGridEncoder2D: L=16, F=2, N=1048576, T=524288. fp16 tables scaled by 4096.
// R8: spatial bucketing (32x32 uv tiles) with BLOCK-AGGREGATED counting sort
// (smem histograms + one global atomic per (block,bin)) replacing the
// contention-bound per-point atomics of R7. Main gather kernel identical to R7.

#define NPTS    1048576
#define TSIZE   524288
#define TMASK   (TSIZE - 1)
#define HPRIME  131101
#define QTOTAL  659835                 // sum of res^2 over dense levels 0..11
#define HBASE   663817                 // float2 index where hashed tables start
#define RPTOTAL (QTOTAL + TSIZE)
#define NBINS   1024
#define SORTBLK 256                    // sort blocks (4096 points each)
#define SCALE_F     4096.0f
#define INV_SCALE_F (1.0f / 4096.0f)

__constant__ int c_res[16] = {16, 22, 30, 42, 58, 80, 111, 153,
                              212, 294, 406, 561, 776, 1072, 1482, 2048};
__constant__ int c_off[16] = {0, 289, 818, 1779, 3628, 7109, 13670, 26214,
                              49930, 95299, 182324, 347973,
                              663817, 1188105, 1712393, 2236681};
__constant__ int c_qoff[12] = {0, 256, 740, 1640, 3404, 6768, 13168,
                               25489, 48898, 93842, 180278, 345114};

// 10.6 MB: dense cell (l,x,y) -> {v00,v01,v10,v11} as 4 half2 (16B aligned).
__device__ __align__(16) __half2 g_qh[(size_t)QTOTAL * 4];
// 8.4 MB: 16B-aligned fp16 mirror of the 4 hashed level tables.
__device__ __align__(16) __half2 g_hh[4 * TSIZE];

// bucketing state (rebuilt every replay)
__device__ int    g_hist[NBINS];
__device__ int    g_binbase[NBINS];
__device__ int    g_fill[NBINS];
__device__ int    g_perm[NPTS];
__device__ __align__(8) float2 g_uvs[NPTS];

__device__ __forceinline__ __half2 sc_h2(float2 v) {
    return __floats2half2_rn(v.x * SCALE_F, v.y * SCALE_F);
}

__device__ __forceinline__ int bin_of(float2 p) {
    int kx = min((int)(p.x * 32.0f), 31);
    int ky = min((int)(p.y * 32.0f), 31);
    return ky * 32 + kx;
}

__global__ void zero_kernel() {
    int t = blockIdx.x * blockDim.x + threadIdx.x;
    if (t < NBINS) { g_hist[t] = 0; g_fill[t] = 0; }
}

// 256 blocks x 1024 threads x 4 points: smem histogram, aggregated global adds.
__global__ void __launch_bounds__(1024)
hist_kernel(const float2* __restrict__ uv)
{
    __shared__ int s_h[NBINS];
    int tid = threadIdx.x;
    s_h[tid] = 0;
    __syncthreads();

    int base = blockIdx.x * 4096;
#pragma unroll
    for (int i = 0; i < 4; i++) {
        float2 p = __ldg(&uv[base + i * 1024 + tid]);
        atomicAdd(&s_h[bin_of(p)], 1);
    }
    __syncthreads();

    int c = s_h[tid];
    if (c) atomicAdd(&g_hist[tid], c);
}

__global__ void __launch_bounds__(NBINS)
scan_kernel() {
    __shared__ int s[NBINS];
    int t = threadIdx.x;
    int h = g_hist[t];
    s[t] = h;
    __syncthreads();
#pragma unroll
    for (int off = 1; off < NBINS; off <<= 1) {
        int v = (t >= off) ? s[t - off] : 0;
        __syncthreads();
        s[t] += v;
        __syncthreads();
    }
    g_binbase[t] = s[t] - h;   // exclusive prefix
}

// 256 blocks x 1024 threads x 4 points: local ranks via smem atomics,
// one aggregated global atomic per (block,bin), then direct writes.
__global__ void __launch_bounds__(1024)
scatter_kernel(const float2* __restrict__ uv)
{
    __shared__ int s_cnt[NBINS];
    __shared__ int s_off[NBINS];
    int tid = threadIdx.x;
    s_cnt[tid] = 0;
    __syncthreads();

    int base = blockIdx.x * 4096;
    float2 p[4];
    int    b[4], r[4];
#pragma unroll
    for (int i = 0; i < 4; i++) {
        p[i] = __ldg(&uv[base + i * 1024 + tid]);
        b[i] = bin_of(p[i]);
        r[i] = atomicAdd(&s_cnt[b[i]], 1);
    }
    __syncthreads();

    int c = s_cnt[tid];
    s_off[tid] = c ? atomicAdd(&g_fill[tid], c) : 0;
    __syncthreads();

#pragma unroll
    for (int i = 0; i < 4; i++) {
        int pos = g_binbase[b[i]] + s_off[b[i]] + r[i];
        g_uvs[pos]  = p[i];
        g_perm[pos] = base + i * 1024 + tid;
    }
}

__global__ void __launch_bounds__(256)
repack_kernel(const float2* __restrict__ lat)
{
    int c = blockIdx.x * blockDim.x + threadIdx.x;
    if (c >= RPTOTAL) return;

    if (c >= QTOTAL) {
        int base = (c - QTOTAL) * 4;
        __half2 h0 = sc_h2(lat[HBASE + base + 0]);
        __half2 h1 = sc_h2(lat[HBASE + base + 1]);
        __half2 h2 = sc_h2(lat[HBASE + base + 2]);
        __half2 h3 = sc_h2(lat[HBASE + base + 3]);
        float4 v;
        ((__half2*)&v)[0] = h0; ((__half2*)&v)[1] = h1;
        ((__half2*)&v)[2] = h2; ((__half2*)&v)[3] = h3;
        *(float4*)(g_hh + base) = v;
        return;
    }

    int l = 0;
#pragma unroll
    for (int i = 1; i < 12; i++) l += (c >= c_qoff[i]);

    int local = c - c_qoff[l];
    int res   = c_res[l];
    int x     = local / res;
    int y     = local - x * res;
    int base  = c_off[l] + x * res + y;

    __half2 h00 = sc_h2(lat[base]);
    __half2 h01 = sc_h2(lat[base + 1]);
    __half2 h10 = sc_h2(lat[base + res]);
    __half2 h11 = sc_h2(lat[base + res + 1]);

    float4 v;
    ((__half2*)&v)[0] = h00; ((__half2*)&v)[1] = h01;
    ((__half2*)&v)[2] = h10; ((__half2*)&v)[3] = h11;
    *(float4*)(g_qh + (size_t)c * 4) = v;
}

__global__ void __launch_bounds__(256)
hashgrid2d_kernel(float4* __restrict__ out)
{
    __shared__ float2 s_uv[32];
    __shared__ int    s_pn[32];
    __shared__ float4 s_tr[256];

    int tid = threadIdx.x;
    int w   = tid >> 5;          // slot: levels {2w, 2w+1}
    int ln  = tid & 31;
    int n0  = blockIdx.x * 32;

    if (w == 0) {
        s_uv[ln] = g_uvs[n0 + ln];
        s_pn[ln] = g_perm[n0 + ln];
    }
    __syncthreads();
    float2 p = s_uv[ln];

    float r0, r1, r2, r3;

    if (w < 6) {
        // ---- two dense levels: one 16B quad load each ----
        float rr[4];
#pragma unroll
        for (int k = 0; k < 2; k++) {
            int l   = 2 * w + k;
            int res = c_res[l];

            float fres = (float)res;
            float sx = p.x * fres;
            float sy = p.y * fres;
            float fx = floorf(sx);
            float fy = floorf(sy);
            int   x0 = (int)fx;
            int   y0 = (int)fy;
            float px = sx - fx;
            float py = sy - fy;

            float4 raw = *(const float4*)(g_qh + (size_t)(c_qoff[l] + x0 * res + y0) * 4);
            const __half2* h = (const __half2*)&raw;
            float2 v00 = __half22float2(h[0]);
            float2 v01 = __half22float2(h[1]);
            float2 v10 = __half22float2(h[2]);
            float2 v11 = __half22float2(h[3]);

            float qx = 1.0f - px;
            float qy = 1.0f - py;
            float w00 = qx * qy;
            float w01 = qx * py;
            float w10 = px * qy;
            float w11 = px * py;

            rr[2 * k + 0] = v00.x * w00 + v01.x * w01 + v10.x * w10 + v11.x * w11;
            rr[2 * k + 1] = v00.y * w00 + v01.y * w01 + v10.y * w10 + v11.y * w11;
        }
        r0 = rr[0]; r1 = rr[1]; r2 = rr[2]; r3 = rr[3];
    } else {
        // ---- two hashed levels: 16B group-of-4 loads + weight scatter ----
        float rr[4];
#pragma unroll
        for (int k = 0; k < 2; k++) {
            int l = 12 + (w - 6) * 2 + k;

            float fres = (float)c_res[l];
            float sx = p.x * fres;
            float sy = p.y * fres;
            float fx = floorf(sx);
            float fy = floorf(sy);
            int   x0 = (int)fx;
            int   y0 = (int)fy;
            float px = sx - fx;
            float py = sy - fy;

            float qx = 1.0f - px;
            float qy = 1.0f - py;

            const __half2* H = g_hh + (size_t)(l - 12) * TSIZE;

            int hy0 = y0 * HPRIME;
            int hy1 = hy0 + HPRIME;
            int i0  = (x0 ^ hy0) & TMASK;
            int i1  = (x0 ^ hy1) & TMASK;

            float4 raw0 = *(const float4*)(H + (i0 & ~3));
            float4 raw1 = *(const float4*)(H + (i1 & ~3));
            const __half2* v0 = (const __half2*)&raw0;
            const __half2* v1 = (const __half2*)&raw1;

            int  d   = ((x0 + 1) ^ x0) & 3;        // 1 or 3
            bool ing = (x0 & 3) != 3;              // x0+1 in same 16B group?
            float wpx = ing ? px : 0.0f;

            int pA0 = i0 & 3, pB0 = pA0 ^ d;
            int pA1 = i1 & 3, pB1 = pA1 ^ d;

            float e0x = 0.f, e0y = 0.f, e1x = 0.f, e1y = 0.f;
#pragma unroll
            for (int t = 0; t < 4; t++) {
                float wt0 = (t == pA0) ? qx : ((t == pB0) ? wpx : 0.0f);
                float wt1 = (t == pA1) ? qx : ((t == pB1) ? wpx : 0.0f);
                float2 a = __half22float2(v0[t]);
                float2 b = __half22float2(v1[t]);
                e0x += wt0 * a.x; e0y += wt0 * a.y;
                e1x += wt1 * b.x; e1y += wt1 * b.y;
            }

            if (!ing) {
                int x1 = x0 + 1;
                float2 f0 = __half22float2(H[(x1 ^ hy0) & TMASK]);
                float2 f1 = __half22float2(H[(x1 ^ hy1) & TMASK]);
                e0x += px * f0.x; e0y += px * f0.y;
                e1x += px * f1.x; e1y += px * f1.y;
            }

            rr[2 * k + 0] = qy * e0x + py * e1x;
            rr[2 * k + 1] = qy * e0y + py * e1y;
        }
        r0 = rr[0]; r1 = rr[1]; r2 = rr[2]; r3 = rr[3];
    }

    r0 *= INV_SCALE_F; r1 *= INV_SCALE_F; r2 *= INV_SCALE_F; r3 *= INV_SCALE_F;

    // XOR-swizzled transpose; store to each point's ORIGINAL slot (one 128B
    // line per point -> same wavefront count as a coalesced store).
    s_tr[ln * 8 + (w ^ (ln & 7))] = make_float4(r0, r1, r2, r3);
    __syncthreads();

    int jj = tid & 7;
    int ll = tid >> 3;
    int pn = s_pn[ll];
    out[(size_t)pn * 8 + jj] = s_tr[ll * 8 + (jj ^ (ll & 7))];
}

extern "C" void kernel_launch(void* const* d_in, const int* in_sizes, int n_in,
                              void* d_out, int out_size)
{
    const float2* uv  = (const float2*)d_in[0];
    const float2* lat = (const float2*)d_in[1];
    float4*       out = (float4*)d_out;

    zero_kernel<<<4, 256>>>();
    hist_kernel<<<SORTBLK, 1024>>>(uv);
    scan_kernel<<<1, NBINS>>>();
    scatter_kernel<<<SORTBLK, 1024>>>(uv);
    repack_kernel<<<(RPTOTAL + 255) / 256, 256>>>(lat);

    hashgrid2d_kernel<<<NPTS / 32, 256>>>(out);
}

// round 9
// speedup vs baseline: 2.3425x; 1.0913x over previous
#include <cuda_runtime.h>
#include <cuda_fp16.h>

// HashGridEncoder2D: L=16, F=2, N=1048576, T=524288. fp16 tables scaled by 4096.
// R9: 64x64-bin aggregated counting sort with packed (uv,perm) float4 records,
// repack fused into the hist launch, g_fill zeroed in scan.
// Main gather kernel: slot-warp (warp = level pair for 32 sorted points),
// dense = 16B quad LDG, hashed = 16B group-of-4 + branchless weight scatter.

#define NPTS    1048576
#define TSIZE   524288
#define TMASK   (TSIZE - 1)
#define HPRIME  131101
#define QTOTAL  659835                 // sum of res^2 over dense levels 0..11
#define HBASE   663817                 // float2 index where hashed tables start
#define RPTOTAL (QTOTAL + TSIZE)
#define RPBLK   ((RPTOTAL + 255) / 256)
#define NBINS   4096
#define HISTBLK 256                    // hist blocks (4096 points each)
#define SCTBLK  512                    // scatter blocks (2048 points each)
#define SCALE_F     4096.0f
#define INV_SCALE_F (1.0f / 4096.0f)

__constant__ int c_res[16] = {16, 22, 30, 42, 58, 80, 111, 153,
                              212, 294, 406, 561, 776, 1072, 1482, 2048};
__constant__ int c_off[16] = {0, 289, 818, 1779, 3628, 7109, 13670, 26214,
                              49930, 95299, 182324, 347973,
                              663817, 1188105, 1712393, 2236681};
__constant__ int c_qoff[12] = {0, 256, 740, 1640, 3404, 6768, 13168,
                               25489, 48898, 93842, 180278, 345114};

// 10.6 MB: dense cell (l,x,y) -> {v00,v01,v10,v11} as 4 half2 (16B aligned).
__device__ __align__(16) __half2 g_qh[(size_t)QTOTAL * 4];
// 8.4 MB: 16B-aligned fp16 mirror of the 4 hashed level tables.
__device__ __align__(16) __half2 g_hh[4 * TSIZE];

// bucketing state (rebuilt every replay)
__device__ int    g_hist[NBINS];
__device__ int    g_binbase[NBINS];
__device__ int    g_fill[NBINS];
__device__ __align__(16) float4 g_uvp[NPTS];   // {u, v, perm-as-int, 0}

__device__ __forceinline__ __half2 sc_h2(float2 v) {
    return __floats2half2_rn(v.x * SCALE_F, v.y * SCALE_F);
}

__device__ __forceinline__ int bin_of(float px, float py) {
    int kx = min((int)(px * 64.0f), 63);
    int ky = min((int)(py * 64.0f), 63);
    return ky * 64 + kx;
}

__global__ void zero_kernel() {
    g_hist[blockIdx.x * blockDim.x + threadIdx.x] = 0;
}

// Fused: blocks [0, HISTBLK) build the histogram, blocks [HISTBLK, ...) repack tables.
__global__ void __launch_bounds__(256)
hist_repack_kernel(const float2* __restrict__ uv, const float2* __restrict__ lat)
{
    if (blockIdx.x < HISTBLK) {
        __shared__ int s_h[NBINS];
        int tid = threadIdx.x;
#pragma unroll
        for (int i = 0; i < NBINS / 256; i++) s_h[tid + i * 256] = 0;
        __syncthreads();

        const float4* uv4 = (const float4*)uv;   // 2 points per float4
        int base4 = blockIdx.x * 2048;           // 4096 points per block
#pragma unroll
        for (int i = 0; i < 8; i++) {
            float4 q = __ldg(&uv4[base4 + i * 256 + tid]);
            atomicAdd(&s_h[bin_of(q.x, q.y)], 1);
            atomicAdd(&s_h[bin_of(q.z, q.w)], 1);
        }
        __syncthreads();

#pragma unroll
        for (int i = 0; i < NBINS / 256; i++) {
            int b = tid + i * 256;
            int c = s_h[b];
            if (c) atomicAdd(&g_hist[b], c);
        }
        return;
    }

    int c = (blockIdx.x - HISTBLK) * 256 + threadIdx.x;
    if (c >= RPTOTAL) return;

    if (c >= QTOTAL) {
        int base = (c - QTOTAL) * 4;
        __half2 h0 = sc_h2(lat[HBASE + base + 0]);
        __half2 h1 = sc_h2(lat[HBASE + base + 1]);
        __half2 h2 = sc_h2(lat[HBASE + base + 2]);
        __half2 h3 = sc_h2(lat[HBASE + base + 3]);
        float4 v;
        ((__half2*)&v)[0] = h0; ((__half2*)&v)[1] = h1;
        ((__half2*)&v)[2] = h2; ((__half2*)&v)[3] = h3;
        *(float4*)(g_hh + base) = v;
        return;
    }

    int l = 0;
#pragma unroll
    for (int i = 1; i < 12; i++) l += (c >= c_qoff[i]);

    int local = c - c_qoff[l];
    int res   = c_res[l];
    int x     = local / res;
    int y     = local - x * res;
    int base  = c_off[l] + x * res + y;

    __half2 h00 = sc_h2(lat[base]);
    __half2 h01 = sc_h2(lat[base + 1]);
    __half2 h10 = sc_h2(lat[base + res]);
    __half2 h11 = sc_h2(lat[base + res + 1]);

    float4 v;
    ((__half2*)&v)[0] = h00; ((__half2*)&v)[1] = h01;
    ((__half2*)&v)[2] = h10; ((__half2*)&v)[3] = h11;
    *(float4*)(g_qh + (size_t)c * 4) = v;
}

// 4096-bin exclusive scan (1024 threads, 4 bins each) + zero g_fill.
__global__ void __launch_bounds__(1024)
scan_kernel() {
    __shared__ int s[1024];
    int t = threadIdx.x;
    int v0 = g_hist[4 * t + 0];
    int v1 = g_hist[4 * t + 1];
    int v2 = g_hist[4 * t + 2];
    int v3 = g_hist[4 * t + 3];
    int sum = v0 + v1 + v2 + v3;
    s[t] = sum;
    __syncthreads();
#pragma unroll
    for (int off = 1; off < 1024; off <<= 1) {
        int v = (t >= off) ? s[t - off] : 0;
        __syncthreads();
        s[t] += v;
        __syncthreads();
    }
    int excl = s[t] - sum;
    g_binbase[4 * t + 0] = excl;
    g_binbase[4 * t + 1] = excl + v0;
    g_binbase[4 * t + 2] = excl + v0 + v1;
    g_binbase[4 * t + 3] = excl + v0 + v1 + v2;
    g_fill[4 * t + 0] = 0;
    g_fill[4 * t + 1] = 0;
    g_fill[4 * t + 2] = 0;
    g_fill[4 * t + 3] = 0;
}

// 512 blocks x 1024 threads x 2 points: smem ranks, aggregated global adds,
// one packed 16B store per point.
__global__ void __launch_bounds__(1024)
scatter_kernel(const float2* __restrict__ uv)
{
    __shared__ int s_cnt[NBINS];
    __shared__ int s_off[NBINS];
    int tid = threadIdx.x;
#pragma unroll
    for (int i = 0; i < NBINS / 1024; i++) s_cnt[tid + i * 1024] = 0;
    __syncthreads();

    const float4* uv4 = (const float4*)uv;
    int base4 = blockIdx.x * 1024;           // 2048 points per block
    float4 q = __ldg(&uv4[base4 + tid]);
    int n0 = (base4 + tid) * 2;

    int b0 = bin_of(q.x, q.y);
    int b1 = bin_of(q.z, q.w);
    int r0 = atomicAdd(&s_cnt[b0], 1);
    int r1 = atomicAdd(&s_cnt[b1], 1);
    __syncthreads();

#pragma unroll
    for (int i = 0; i < NBINS / 1024; i++) {
        int b = tid + i * 1024;
        int c = s_cnt[b];
        s_off[b] = c ? atomicAdd(&g_fill[b], c) : 0;
    }
    __syncthreads();

    int pos0 = g_binbase[b0] + s_off[b0] + r0;
    int pos1 = g_binbase[b1] + s_off[b1] + r1;
    g_uvp[pos0] = make_float4(q.x, q.y, __int_as_float(n0), 0.0f);
    g_uvp[pos1] = make_float4(q.z, q.w, __int_as_float(n0 + 1), 0.0f);
}

__global__ void __launch_bounds__(256)
hashgrid2d_kernel(float4* __restrict__ out)
{
    __shared__ float2 s_uv[32];
    __shared__ int    s_pn[32];
    __shared__ float4 s_tr[256];

    int tid = threadIdx.x;
    int w   = tid >> 5;          // slot: levels {2w, 2w+1}
    int ln  = tid & 31;
    int n0  = blockIdx.x * 32;

    if (w == 0) {
        float4 q = g_uvp[n0 + ln];
        s_uv[ln] = make_float2(q.x, q.y);
        s_pn[ln] = __float_as_int(q.z);
    }
    __syncthreads();
    float2 p = s_uv[ln];

    float r0, r1, r2, r3;

    if (w < 6) {
        // ---- two dense levels: one 16B quad load each ----
        float rr[4];
#pragma unroll
        for (int k = 0; k < 2; k++) {
            int l   = 2 * w + k;
            int res = c_res[l];

            float fres = (float)res;
            float sx = p.x * fres;
            float sy = p.y * fres;
            float fx = floorf(sx);
            float fy = floorf(sy);
            int   x0 = (int)fx;
            int   y0 = (int)fy;
            float px = sx - fx;
            float py = sy - fy;

            float4 raw = *(const float4*)(g_qh + (size_t)(c_qoff[l] + x0 * res + y0) * 4);
            const __half2* h = (const __half2*)&raw;
            float2 v00 = __half22float2(h[0]);
            float2 v01 = __half22float2(h[1]);
            float2 v10 = __half22float2(h[2]);
            float2 v11 = __half22float2(h[3]);

            float qx = 1.0f - px;
            float qy = 1.0f - py;
            float w00 = qx * qy;
            float w01 = qx * py;
            float w10 = px * qy;
            float w11 = px * py;

            rr[2 * k + 0] = v00.x * w00 + v01.x * w01 + v10.x * w10 + v11.x * w11;
            rr[2 * k + 1] = v00.y * w00 + v01.y * w01 + v10.y * w10 + v11.y * w11;
        }
        r0 = rr[0]; r1 = rr[1]; r2 = rr[2]; r3 = rr[3];
    } else {
        // ---- two hashed levels: 16B group-of-4 loads + weight scatter ----
        float rr[4];
#pragma unroll
        for (int k = 0; k < 2; k++) {
            int l = 12 + (w - 6) * 2 + k;

            float fres = (float)c_res[l];
            float sx = p.x * fres;
            float sy = p.y * fres;
            float fx = floorf(sx);
            float fy = floorf(sy);
            int   x0 = (int)fx;
            int   y0 = (int)fy;
            float px = sx - fx;
            float py = sy - fy;

            float qx = 1.0f - px;
            float qy = 1.0f - py;

            const __half2* H = g_hh + (size_t)(l - 12) * TSIZE;

            int hy0 = y0 * HPRIME;
            int hy1 = hy0 + HPRIME;
            int i0  = (x0 ^ hy0) & TMASK;
            int i1  = (x0 ^ hy1) & TMASK;

            float4 raw0 = *(const float4*)(H + (i0 & ~3));
            float4 raw1 = *(const float4*)(H + (i1 & ~3));
            const __half2* v0 = (const __half2*)&raw0;
            const __half2* v1 = (const __half2*)&raw1;

            int  d   = ((x0 + 1) ^ x0) & 3;        // 1 or 3
            bool ing = (x0 & 3) != 3;              // x0+1 in same 16B group?
            float wpx = ing ? px : 0.0f;

            int pA0 = i0 & 3, pB0 = pA0 ^ d;
            int pA1 = i1 & 3, pB1 = pA1 ^ d;

            float e0x = 0.f, e0y = 0.f, e1x = 0.f, e1y = 0.f;
#pragma unroll
            for (int t = 0; t < 4; t++) {
                float wt0 = (t == pA0) ? qx : ((t == pB0) ? wpx : 0.0f);
                float wt1 = (t == pA1) ? qx : ((t == pB1) ? wpx : 0.0f);
                float2 a = __half22float2(v0[t]);
                float2 b = __half22float2(v1[t]);
                e0x += wt0 * a.x; e0y += wt0 * a.y;
                e1x += wt1 * b.x; e1y += wt1 * b.y;
            }

            if (!ing) {
                int x1 = x0 + 1;
                float2 f0 = __half22float2(H[(x1 ^ hy0) & TMASK]);
                float2 f1 = __half22float2(H[(x1 ^ hy1) & TMASK]);
                e0x += px * f0.x; e0y += px * f0.y;
                e1x += px * f1.x; e1y += px * f1.y;
            }

            rr[2 * k + 0] = qy * e0x + py * e1x;
            rr[2 * k + 1] = qy * e0y + py * e1y;
        }
        r0 = rr[0]; r1 = rr[1]; r2 = rr[2]; r3 = rr[3];
    }

    r0 *= INV_SCALE_F; r1 *= INV_SCALE_F; r2 *= INV_SCALE_F; r3 *= INV_SCALE_F;

    // XOR-swizzled transpose; store to each point's ORIGINAL slot (one 128B
    // line per point -> same wavefront count as a coalesced store).
    s_tr[ln * 8 + (w ^ (ln & 7))] = make_float4(r0, r1, r2, r3);
    __syncthreads();

    int jj = tid & 7;
    int ll = tid >> 3;
    int pn = s_pn[ll];
    out[(size_t)pn * 8 + jj] = s_tr[ll * 8 + (jj ^ (ll & 7))];
}

extern "C" void kernel_launch(void* const* d_in, const int* in_sizes, int n_in,
                              void* d_out, int out_size)
{
    const float2* uv  = (const float2*)d_in[0];
    const float2* lat = (const float2*)d_in[1];
    float4*       out = (float4*)d_out;

    zero_kernel<<<NBINS / 256, 256>>>();
    hist_repack_kernel<<<HISTBLK + RPBLK, 256>>>(uv, lat);
    scan_kernel<<<1, 1024>>>();
    scatter_kernel<<<SCTBLK, 1024>>>(uv);

    hashgrid2d_kernel<<<NPTS / 32, 256>>>(out);
}